// round 5
// baseline (speedup 1.0000x reference)
#include <cuda_runtime.h>
#include <math.h>

#define BB 8192
#define NSEQ 29
#define FF 147
#define DD 128
#define DCAT 429
#define NROWS (BB*NSEQ)
#define EPS_BN 1e-5f

// ---------------- scratch ----------------
__device__ float g_z[(size_t)NROWS * DD];   // raw z = xp@Wg, then overwritten in-place by u
__device__ float g_pool[BB * DD];
__device__ float g_p[BB * DD];
__device__ float g_s1[NSEQ], g_q1[NSEQ];
__device__ float g_is1[NSEQ];
__device__ float g_O1[NSEQ * DD];
__device__ float g_s2[NSEQ], g_q2[NSEQ];
__device__ float g_bn2m[NSEQ], g_bn2i[NSEQ];
__device__ float g_v[DD];
__device__ float g_s3[DD], g_q3[DD];
__device__ float g_bn3m[DD], g_bn3i[DD];

#define FMA2(d, a, b) asm("fma.rn.f32x2 %0, %1, %2, %0;" : "+l"(d) : "l"(a), "l"(b))
#define PACK2(d, f)   asm("mov.b64 %0, {%1, %1};" : "=l"(d) : "r"(__float_as_uint(f)))
#define UNPK(lo, hi, p) { unsigned _l,_h; asm("mov.b64 {%0,%1}, %2;":"=r"(_l),"=r"(_h):"l"(p)); lo=__uint_as_float(_l); hi=__uint_as_float(_h); }

__device__ __forceinline__ void cp_async16(unsigned saddr, const void* g) {
    asm volatile("cp.async.cg.shared.global [%0], [%1], 16;" :: "r"(saddr), "l"(g) : "memory");
}

__device__ __forceinline__ float conv_val(const float* __restrict__ xr, const float* __restrict__ w, int k) {
    float v;
    if (k < 145) {
        v = fmaf(xr[k], w[0], fmaf(xr[k+1], w[1], fmaf(xr[k+2], w[2], w[15])));
    } else if (k < 288) {
        int j = k - 145; v = w[16];
        #pragma unroll
        for (int u = 0; u < 5; u++) v = fmaf(xr[j+u], w[3+u], v);
    } else {
        int j = k - 288; v = w[17];
        #pragma unroll
        for (int u = 0; u < 7; u++) v = fmaf(xr[j+u], w[8+u], v);
    }
    return v;
}

__device__ __forceinline__ void load_ws(float* ws, const float* w1, const float* b1,
    const float* w2, const float* b2, const float* w3, const float* b3, const float* ac) {
    ws[0]=w1[0]; ws[1]=w1[1]; ws[2]=w1[2];
    ws[3]=w2[0]; ws[4]=w2[1]; ws[5]=w2[2]; ws[6]=w2[3]; ws[7]=w2[4];
    ws[8]=w3[0]; ws[9]=w3[1]; ws[10]=w3[2]; ws[11]=w3[3]; ws[12]=w3[4]; ws[13]=w3[5]; ws[14]=w3[6];
    ws[15]=b1[0]; ws[16]=b2[0]; ws[17]=b3[0]; ws[18]=ac[0];
}

// ---------------- k_reset ----------------
__global__ void k_reset() {
    int t = threadIdx.x;
    if (t < NSEQ) { g_s1[t]=0.f; g_q1[t]=0.f; g_s2[t]=0.f; g_q2[t]=0.f; }
    if (t < DD)   { g_s3[t]=0.f; g_q3[t]=0.f; }
}

// ---------------- k_stats1: BN1 moments of prelu(conv) ----------------
__global__ __launch_bounds__(256)
void k_stats1(const float* __restrict__ X, const float* w1, const float* b1,
              const float* w2, const float* b2, const float* w3, const float* b3,
              const float* ac)
{
    __shared__ float Xs[64*149];
    __shared__ float ws[20];
    int t = threadIdx.x;
    long row0 = (long)blockIdx.x * 64;
    const float* Xb = X + row0 * FF;
    for (int e = t; e < 64*FF; e += 256) { int rr = e/FF, j = e - rr*FF; Xs[rr*149+j] = Xb[e]; }
    if (t == 0) load_ws(ws, w1,b1,w2,b2,w3,b3,ac);
    __syncthreads();
    float a = ws[18];
    int r = t >> 2, c = t & 3;
    const float* xr = Xs + r*149;
    float s = 0.f, q = 0.f;
    for (int k = c; k < DCAT; k += 4) {
        float v = conv_val(xr, ws, k);
        v = (v >= 0.f) ? v : a*v;
        s += v; q = fmaf(v, v, q);
    }
    s += __shfl_down_sync(0xffffffffu, s, 2); s += __shfl_down_sync(0xffffffffu, s, 1);
    q += __shfl_down_sync(0xffffffffu, q, 2); q += __shfl_down_sync(0xffffffffu, q, 1);
    if (c == 0) {
        int n = (int)((row0 + r) % NSEQ);
        atomicAdd(&g_s1[n], s);
        atomicAdd(&g_q1[n], q);
    }
}

// ---------------- k_gemm: conv+prelu -> raw z = xp @ Wg (f32x2) ----------------
#define GEMM_SMEM ((64*149 + DCAT*64 + 2*33*128) * 4)
__global__ __launch_bounds__(256, 1)
void k_gemm(const float* __restrict__ X, const float* __restrict__ Wg,
            const float* w1, const float* b1, const float* w2, const float* b2,
            const float* w3, const float* b3, const float* ac)
{
    extern __shared__ float sm[];
    float* Xs  = sm;                 // [64][149]
    float* xcT = Xs + 64*149;        // [429][64], k-major
    float* Wgs = xcT + DCAT*64;      // 2 x [33][128]
    __shared__ float ws[20];
    int t = threadIdx.x;
    long row0 = (long)blockIdx.x * 64;

    { // prefetch Wg chunk 0
        unsigned dst = (unsigned)__cvta_generic_to_shared(Wgs);
        for (int i = t; i < 1056; i += 256) cp_async16(dst + i*16, Wg + i*4);
        asm volatile("cp.async.commit_group;" ::: "memory");
    }
    const float* Xb = X + row0 * FF;
    for (int e = t; e < 64*FF; e += 256) { int rr = e/FF, j = e - rr*FF; Xs[rr*149+j] = Xb[e]; }
    if (t == 0) load_ws(ws, w1,b1,w2,b2,w3,b3,ac);
    __syncthreads();

    float a = ws[18];
    for (int e = t; e < DCAT*64; e += 256) {
        int k = e >> 6, rr = e & 63;
        float v = conv_val(Xs + rr*149, ws, k);
        xcT[k*64 + rr] = (v >= 0.f) ? v : a*v;
    }

    int tc = t & 31, tr = t >> 5;
    unsigned long long acc[4][4];
    #pragma unroll
    for (int i = 0; i < 4; i++)
        #pragma unroll
        for (int j = 0; j < 4; j++) acc[i][j] = 0ull;

    int buf = 0;
    for (int c = 0; c < 13; ++c) {
        if (c < 12) {
            unsigned dst = (unsigned)__cvta_generic_to_shared(Wgs + (buf^1)*4224);
            const float* src = Wg + (c+1)*4224;
            for (int i = t; i < 1056; i += 256) cp_async16(dst + i*16, src + i*4);
            asm volatile("cp.async.commit_group;" ::: "memory");
            asm volatile("cp.async.wait_group 1;" ::: "memory");
        } else {
            asm volatile("cp.async.wait_group 0;" ::: "memory");
        }
        __syncthreads();
        const float* Wc = Wgs + buf*4224;
        const float* Ab = xcT + c*33*64 + tr*8;
        #pragma unroll 3
        for (int kk = 0; kk < 33; ++kk) {
            ulonglong2 p0 = *(const ulonglong2*)(Ab + kk*64);
            ulonglong2 p1 = *(const ulonglong2*)(Ab + kk*64 + 4);
            float4 bv = *(const float4*)(Wc + kk*128 + tc*4);
            unsigned long long b0, b1, b2, b3;
            PACK2(b0, bv.x); PACK2(b1, bv.y); PACK2(b2, bv.z); PACK2(b3, bv.w);
            FMA2(acc[0][0], p0.x, b0); FMA2(acc[0][1], p0.x, b1); FMA2(acc[0][2], p0.x, b2); FMA2(acc[0][3], p0.x, b3);
            FMA2(acc[1][0], p0.y, b0); FMA2(acc[1][1], p0.y, b1); FMA2(acc[1][2], p0.y, b2); FMA2(acc[1][3], p0.y, b3);
            FMA2(acc[2][0], p1.x, b0); FMA2(acc[2][1], p1.x, b1); FMA2(acc[2][2], p1.x, b2); FMA2(acc[2][3], p1.x, b3);
            FMA2(acc[3][0], p1.y, b0); FMA2(acc[3][1], p1.y, b1); FMA2(acc[3][2], p1.y, b2); FMA2(acc[3][3], p1.y, b3);
        }
        __syncthreads();
        buf ^= 1;
    }

    size_t base = (size_t)(row0 + tr*8) * DD + tc*4;
    #pragma unroll
    for (int i = 0; i < 4; i++) {
        float lo[4], hi[4];
        #pragma unroll
        for (int j = 0; j < 4; j++) { UNPK(lo[j], hi[j], acc[i][j]); }
        *(float4*)(g_z + base + (size_t)(2*i)*DD)   = make_float4(lo[0], lo[1], lo[2], lo[3]);
        *(float4*)(g_z + base + (size_t)(2*i+1)*DD) = make_float4(hi[0], hi[1], hi[2], hi[3]);
    }
}

// ---------------- k_fin1: BN1 finalize + affine offset O1 ----------------
__global__ void k_fin1(const float* __restrict__ Wg) {
    __shared__ float m1s[NSEQ], i1s[NSEQ];
    int t = threadIdx.x;                 // 128 threads
    if (t < NSEQ) {
        float cnt = (float)BB * (float)DCAT;
        float m = g_s1[t] / cnt;
        float v = g_q1[t] / cnt - m*m;
        float is = rsqrtf(v + EPS_BN);
        m1s[t] = m; i1s[t] = is; g_is1[t] = is;
    }
    __syncthreads();
    float S = 0.f;
    for (int k = 0; k < DCAT; k++) S += Wg[k*DD + t];
    for (int n = 0; n < NSEQ; n++) g_O1[n*DD + t] = i1s[n] * m1s[n] * S;
}

// ---------------- k_mix: u = prelu(corr @ z_bn + bg), in-place; BN2 stats ----------------
__global__ __launch_bounds__(256)
void k_mix(const float* __restrict__ corr, const float* __restrict__ bg,
           const float* __restrict__ ag)
{
    __shared__ float zs[NSEQ*DD];
    __shared__ float cs[NSEQ*NSEQ];
    __shared__ float i1s[NSEQ], ssum[NSEQ], ssq[NSEQ];
    int t = threadIdx.x, b = blockIdx.x;
    if (t < NSEQ) { i1s[t] = g_is1[t]; ssum[t] = 0.f; ssq[t] = 0.f; }
    __syncthreads();
    float* zg = g_z + (size_t)b * NSEQ * DD;
    for (int i = t; i < NSEQ*DD; i += 256) { int m = i >> 7; zs[i] = zg[i]*i1s[m] - g_O1[i]; }
    const float* cg = corr + (size_t)b * NSEQ * NSEQ;
    for (int i = t; i < NSEQ*NSEQ; i += 256) cs[i] = cg[i];
    __syncthreads();
    float agv = ag[0];
    if (t < 232) {
        int n = t >> 3, qd = t & 7, d0 = qd*16;
        const float* cr = cs + n*NSEQ;
        unsigned long long acc[8];
        #pragma unroll
        for (int j = 0; j < 8; j++) acc[j] = 0ull;
        #pragma unroll 1
        for (int m = 0; m < NSEQ; m++) {
            unsigned long long cd; PACK2(cd, cr[m]);
            const float* zr = zs + m*DD + d0;
            ulonglong2 z0 = *(const ulonglong2*)zr;
            ulonglong2 z1 = *(const ulonglong2*)(zr + 4);
            ulonglong2 z2 = *(const ulonglong2*)(zr + 8);
            ulonglong2 z3 = *(const ulonglong2*)(zr + 12);
            FMA2(acc[0], z0.x, cd); FMA2(acc[1], z0.y, cd);
            FMA2(acc[2], z1.x, cd); FMA2(acc[3], z1.y, cd);
            FMA2(acc[4], z2.x, cd); FMA2(acc[5], z2.y, cd);
            FMA2(acc[6], z3.x, cd); FMA2(acc[7], z3.y, cd);
        }
        float ls = 0.f, lq = 0.f;
        float* zo = zg + n*DD + d0;
        #pragma unroll
        for (int j = 0; j < 8; j++) {
            float lo, hi; UNPK(lo, hi, acc[j]);
            lo += bg[d0 + 2*j]; hi += bg[d0 + 2*j + 1];
            lo = (lo >= 0.f) ? lo : agv*lo;
            hi = (hi >= 0.f) ? hi : agv*hi;
            zo[2*j] = lo; zo[2*j+1] = hi;
            ls += lo + hi; lq += lo*lo + hi*hi;
        }
        atomicAdd(&ssum[n], ls);
        atomicAdd(&ssq[n], lq);
    }
    __syncthreads();
    if (t < NSEQ) { atomicAdd(&g_s2[t], ssum[t]); atomicAdd(&g_q2[t], ssq[t]); }
}

// ---------------- k_fin2: BN2 finalize + combined head vector v ----------------
__global__ void k_fin2(const float* __restrict__ cent, const float* __restrict__ hw) {
    __shared__ float nrm[4];
    int t = threadIdx.x;                 // 128 threads
    if (t < NSEQ) {
        float cnt = (float)BB * (float)DD;
        float m = g_s2[t] / cnt;
        float v = g_q2[t] / cnt - m*m;
        g_bn2m[t] = m; g_bn2i[t] = rsqrtf(v + EPS_BN);
    }
    if (t >= 32 && t < 36) {
        int h = t - 32; float s = 0.f;
        for (int d = 0; d < DD; d++) { float c = cent[h*DD + d]; s = fmaf(c, c, s); }
        nrm[h] = sqrtf(s) + 1e-8f;
    }
    __syncthreads();
    float v = 0.f;
    #pragma unroll
    for (int h = 0; h < 4; h++) v += hw[h] * cent[h*DD + t] / nrm[h];
    g_v[t] = v;
}

// ---------------- k_pool: BN2 apply + cosine-sim softmax pooling ----------------
__global__ __launch_bounds__(128)
void k_pool()
{
    __shared__ float xb[NSEQ*DD];
    __shared__ float vS[DD], m2[NSEQ], i2[NSEQ], aggS[32], CS[32];
    int t = threadIdx.x, b = blockIdx.x;
    if (t < NSEQ) { m2[t] = g_bn2m[t]; i2[t] = g_bn2i[t]; }
    vS[t] = g_v[t];
    __syncthreads();
    const float* ug = g_z + (size_t)b * NSEQ * DD;
    #pragma unroll 1
    for (int n = 0; n < NSEQ; n++) xb[n*DD + t] = (ug[n*DD + t] - m2[n]) * i2[n];
    __syncthreads();
    int w = t >> 5, l = t & 31;
    for (int n = w; n < NSEQ; n += 4) {
        float s2 = 0.f, sa = 0.f;
        #pragma unroll
        for (int dd = 0; dd < 4; dd++) {
            float x = xb[n*DD + l + dd*32];
            s2 = fmaf(x, x, s2);
            sa = fmaf(vS[l + dd*32], x, sa);
        }
        #pragma unroll
        for (int o = 16; o > 0; o >>= 1) {
            s2 += __shfl_down_sync(0xffffffffu, s2, o);
            sa += __shfl_down_sync(0xffffffffu, sa, o);
        }
        if (l == 0) aggS[n] = sa / (sqrtf(s2) + 1e-8f);
    }
    __syncthreads();
    if (w == 0) {
        float a = (l < NSEQ) ? aggS[l] : -1e30f;
        float mx = a;
        #pragma unroll
        for (int o = 16; o > 0; o >>= 1) mx = fmaxf(mx, __shfl_xor_sync(0xffffffffu, mx, o));
        float e = (l < NSEQ) ? expf(a - mx) : 0.f;
        float s = e;
        #pragma unroll
        for (int o = 16; o > 0; o >>= 1) s += __shfl_xor_sync(0xffffffffu, s, o);
        if (l < NSEQ) CS[l] = e / s;
    }
    __syncthreads();
    float p = 0.f;
    #pragma unroll 1
    for (int n = 0; n < NSEQ; n++) p = fmaf(CS[n], xb[n*DD + t], p);
    g_pool[(size_t)b*DD + t] = p;
}

// ---------------- k_projp: p = pooled @ Wp + bp; BN3 stats ----------------
__global__ __launch_bounds__(256)
void k_projp(const float* __restrict__ Wp, const float* __restrict__ bp)
{
    __shared__ float xs[64*DD];
    __shared__ float ss[DD], sq[DD];
    int t = threadIdx.x;
    size_t row0 = (size_t)blockIdx.x * 64;
    for (int i = t; i < 64*DD; i += 256) xs[i] = g_pool[row0*DD + i];
    if (t < DD) { ss[t] = 0.f; sq[t] = 0.f; }
    __syncthreads();
    int tc = t & 31, tr = t >> 5;
    float acc[8][4];
    #pragma unroll
    for (int i = 0; i < 8; i++)
        #pragma unroll
        for (int j = 0; j < 4; j++) acc[i][j] = 0.f;
    for (int k = 0; k < DD; k++) {
        float4 bv = *(const float4*)(Wp + k*DD + tc*4);
        #pragma unroll
        for (int i = 0; i < 8; i++) {
            float a = xs[(tr*8 + i)*DD + k];
            acc[i][0] = fmaf(a, bv.x, acc[i][0]);
            acc[i][1] = fmaf(a, bv.y, acc[i][1]);
            acc[i][2] = fmaf(a, bv.z, acc[i][2]);
            acc[i][3] = fmaf(a, bv.w, acc[i][3]);
        }
    }
    float4 bpv = *(const float4*)(bp + tc*4);
    float csum[4] = {0,0,0,0}, cq[4] = {0,0,0,0};
    #pragma unroll
    for (int i = 0; i < 8; i++) {
        float o0 = acc[i][0] + bpv.x, o1 = acc[i][1] + bpv.y;
        float o2 = acc[i][2] + bpv.z, o3 = acc[i][3] + bpv.w;
        *(float4*)(g_p + (row0 + tr*8 + i)*DD + tc*4) = make_float4(o0, o1, o2, o3);
        csum[0]+=o0; csum[1]+=o1; csum[2]+=o2; csum[3]+=o3;
        cq[0]=fmaf(o0,o0,cq[0]); cq[1]=fmaf(o1,o1,cq[1]); cq[2]=fmaf(o2,o2,cq[2]); cq[3]=fmaf(o3,o3,cq[3]);
    }
    #pragma unroll
    for (int j = 0; j < 4; j++) { atomicAdd(&ss[tc*4+j], csum[j]); atomicAdd(&sq[tc*4+j], cq[j]); }
    __syncthreads();
    if (t < DD) { atomicAdd(&g_s3[t], ss[t]); atomicAdd(&g_q3[t], sq[t]); }
}

__global__ void k_fin3() {
    int t = threadIdx.x;
    if (t < DD) {
        float m = g_s3[t] / (float)BB;
        float v = g_q3[t] / (float)BB - m*m;
        g_bn3m[t] = m; g_bn3i[t] = rsqrtf(v + EPS_BN);
    }
}

// ---------------- k_mlp: BN3 + prelu(x@Wm1+bm1) @ Wm2 + bm2 -> sigmoid ----------------
__global__ __launch_bounds__(128)
void k_mlp(const float* __restrict__ Wm1, const float* __restrict__ bm1,
           const float* __restrict__ am, const float* __restrict__ Wm2,
           const float* __restrict__ bm2, float* __restrict__ out)
{
    __shared__ float xbn[16*DD];
    __shared__ float sg[16*DD];
    int t = threadIdx.x;
    size_t row0 = (size_t)blockIdx.x * 16;
    for (int i = t; i < 16*DD; i += 128) {
        int k = i & 127;
        xbn[i] = (g_p[row0*DD + i] - g_bn3m[k]) * g_bn3i[k];
    }
    __syncthreads();
    float amv = am[0], w2 = Wm2[t], b1v = bm1[t];
    float acc[16];
    #pragma unroll
    for (int r = 0; r < 16; r++) acc[r] = b1v;
    #pragma unroll 4
    for (int k = 0; k < DD; k++) {
        float wv = Wm1[k*DD + t];
        #pragma unroll
        for (int r = 0; r < 16; r++) acc[r] = fmaf(xbn[r*DD + k], wv, acc[r]);
    }
    #pragma unroll
    for (int r = 0; r < 16; r++) {
        float h = acc[r];
        h = (h >= 0.f) ? h : amv*h;
        sg[r*DD + t] = h * w2;
    }
    __syncthreads();
    int w = t >> 5, l = t & 31;
    float b2 = bm2[0];
    #pragma unroll
    for (int rr = 0; rr < 4; rr++) {
        int r = w*4 + rr;
        float s = sg[r*DD + l] + sg[r*DD + l + 32] + sg[r*DD + l + 64] + sg[r*DD + l + 96];
        #pragma unroll
        for (int o = 16; o > 0; o >>= 1) s += __shfl_down_sync(0xffffffffu, s, o);
        if (l == 0) out[row0 + r] = 1.f / (1.f + expf(-(s + b2)));
    }
}

// ---------------- launch ----------------
extern "C" void kernel_launch(void* const* d_in, const int* in_sizes, int n_in,
                              void* d_out, int out_size) {
    const float* X    = (const float*)d_in[0];
    const float* corr = (const float*)d_in[1];
    const float* w1   = (const float*)d_in[2];
    const float* b1   = (const float*)d_in[3];
    const float* w2   = (const float*)d_in[4];
    const float* b2   = (const float*)d_in[5];
    const float* w3   = (const float*)d_in[6];
    const float* b3   = (const float*)d_in[7];
    const float* ac   = (const float*)d_in[8];
    const float* Wg   = (const float*)d_in[9];
    const float* bg   = (const float*)d_in[10];
    const float* ag   = (const float*)d_in[11];
    const float* cent = (const float*)d_in[12];
    const float* hw   = (const float*)d_in[13];
    const float* Wp   = (const float*)d_in[14];
    const float* bp   = (const float*)d_in[15];
    const float* Wm1  = (const float*)d_in[16];
    const float* bm1  = (const float*)d_in[17];
    const float* am   = (const float*)d_in[18];
    const float* Wm2  = (const float*)d_in[19];
    const float* bm2  = (const float*)d_in[20];
    float* out = (float*)d_out;

    cudaFuncSetAttribute(k_gemm, cudaFuncAttributeMaxDynamicSharedMemorySize, GEMM_SMEM);

    k_reset<<<1, 128>>>();
    k_stats1<<<NROWS/64, 256>>>(X, w1, b1, w2, b2, w3, b3, ac);
    k_gemm<<<NROWS/64, 256, GEMM_SMEM>>>(X, Wg, w1, b1, w2, b2, w3, b3, ac);
    k_fin1<<<1, 128>>>(Wg);
    k_mix<<<BB, 256>>>(corr, bg, ag);
    k_fin2<<<1, 128>>>(cent, hw);
    k_pool<<<BB, 128>>>();
    k_projp<<<BB/64, 256>>>(Wp, bp);
    k_fin3<<<1, 128>>>();
    k_mlp<<<BB/16, 128>>>(Wm1, bm1, am, Wm2, bm2, out);
}

// round 10
// speedup vs baseline: 1.1145x; 1.1145x over previous
#include <cuda_runtime.h>
#include <cuda_bf16.h>
#include <math.h>
#include <stdint.h>

#define BB 8192
#define NSEQ 29
#define FF 147
#define DD 128
#define DCAT 429
#define NROWS (BB*NSEQ)
#define TM 32
#define EPS_BN 1e-5f

// ---------------- scratch ----------------
__device__ float g_z[(size_t)NROWS * DD];   // raw z = xp@Wg, then overwritten in-place by u
__device__ float g_pool[BB * DD];
__device__ float g_p[BB * DD];
__device__ float g_s1[NSEQ], g_q1[NSEQ];
__device__ float g_is1[NSEQ];
__device__ float g_O1[NSEQ * DD];
__device__ float g_s2[NSEQ], g_q2[NSEQ];
__device__ float g_bn2m[NSEQ], g_bn2i[NSEQ];
__device__ float g_v[DD];
__device__ float g_s3[DD], g_q3[DD];
__device__ float g_bn3m[DD], g_bn3i[DD];

#define FMA2(d, a, b) asm("fma.rn.f32x2 %0, %1, %2, %0;" : "+l"(d) : "l"(a), "l"(b))
#define PACK2(d, f)   asm("mov.b64 %0, {%1, %1};" : "=l"(d) : "r"(__float_as_uint(f)))
#define UNPK(lo, hi, p) { unsigned _l,_h; asm("mov.b64 {%0,%1}, %2;":"=r"(_l),"=r"(_h):"l"(p)); lo=__uint_as_float(_l); hi=__uint_as_float(_h); }

__device__ __forceinline__ void cp_async16(unsigned saddr, const void* g) {
    asm volatile("cp.async.cg.shared.global [%0], [%1], 16;" :: "r"(saddr), "l"(g) : "memory");
}

__device__ __forceinline__ float conv_val(const float* __restrict__ xr, const float* __restrict__ w, int k) {
    float v;
    if (k < 145) {
        v = fmaf(xr[k], w[0], fmaf(xr[k+1], w[1], fmaf(xr[k+2], w[2], w[15])));
    } else if (k < 288) {
        int j = k - 145; v = w[16];
        #pragma unroll
        for (int u = 0; u < 5; u++) v = fmaf(xr[j+u], w[3+u], v);
    } else {
        int j = k - 288; v = w[17];
        #pragma unroll
        for (int u = 0; u < 7; u++) v = fmaf(xr[j+u], w[8+u], v);
    }
    return v;
}

__device__ __forceinline__ void load_ws(float* ws, const float* w1, const float* b1,
    const float* w2, const float* b2, const float* w3, const float* b3, const float* ac) {
    ws[0]=w1[0]; ws[1]=w1[1]; ws[2]=w1[2];
    ws[3]=w2[0]; ws[4]=w2[1]; ws[5]=w2[2]; ws[6]=w2[3]; ws[7]=w2[4];
    ws[8]=w3[0]; ws[9]=w3[1]; ws[10]=w3[2]; ws[11]=w3[3]; ws[12]=w3[4]; ws[13]=w3[5]; ws[14]=w3[6];
    ws[15]=b1[0]; ws[16]=b2[0]; ws[17]=b3[0]; ws[18]=ac[0];
}

// ---------------- k_reset ----------------
__global__ void k_reset() {
    int t = threadIdx.x;
    if (t < NSEQ) { g_s1[t]=0.f; g_q1[t]=0.f; g_s2[t]=0.f; g_q2[t]=0.f; }
    if (t < DD)   { g_s3[t]=0.f; g_q3[t]=0.f; }
}

// ---------------- k_gemm: conv+prelu (+BN1 stats) -> raw z = xp @ Wg (f32x2) ----------------
// smem floats: Xs 32*149 + xcT 429*32 + Wg 2*33*128 = 26944 floats = 107776 B -> 2 CTA/SM
#define GEMM_SMEM ((TM*149 + DCAT*TM + 2*33*128) * 4)

__global__ __launch_bounds__(256, 2)
void k_gemm(const float* __restrict__ X, const float* __restrict__ Wg,
            const float* w1, const float* b1, const float* w2, const float* b2,
            const float* w3, const float* b3, const float* ac)
{
    extern __shared__ float sm[];
    float* Xs  = sm;                  // [32][149]
    float* xcT = Xs + TM*149;         // [429][32], k-major
    float* Wgs = xcT + DCAT*TM;       // 2 x [33][128]
    __shared__ float ws[20];
    __shared__ float sS[TM], sQ[TM];

    int t = threadIdx.x;
    long row0 = (long)blockIdx.x * TM;

    { // prefetch Wg chunk 0 (group 0)
        unsigned dst = (unsigned)__cvta_generic_to_shared(Wgs);
        for (int i = t; i < 1056; i += 256) cp_async16(dst + i*16, Wg + i*4);
        asm volatile("cp.async.commit_group;" ::: "memory");
    }
    const float* Xb = X + row0 * FF;
    for (int e = t; e < TM*FF; e += 256) { int rr = e/FF, j = e - rr*FF; Xs[rr*149+j] = Xb[e]; }
    if (t == 0) load_ws(ws, w1,b1,w2,b2,w3,b3,ac);
    if (t < TM) { sS[t] = 0.f; sQ[t] = 0.f; }
    __syncthreads();

    // conv + prelu into xcT; fused BN1 moment accumulation (thread t owns row t&31)
    float a = ws[18];
    int rr = t & 31;
    {
        const float* xr = Xs + rr*149;
        float ls = 0.f, lq = 0.f;
        for (int e = t; e < DCAT*TM; e += 256) {
            int k = e >> 5;
            float v = conv_val(xr, ws, k);
            v = (v >= 0.f) ? v : a*v;
            xcT[k*TM + rr] = v;
            ls += v; lq = fmaf(v, v, lq);
        }
        atomicAdd(&sS[rr], ls);
        atomicAdd(&sQ[rr], lq);
    }

    int tc = t & 31, tr = t >> 5;
    unsigned long long acc[2][4];
    #pragma unroll
    for (int i = 0; i < 2; i++)
        #pragma unroll
        for (int j = 0; j < 4; j++) acc[i][j] = 0ull;

    int buf = 0;
    for (int c = 0; c < 13; ++c) {
        if (c < 12) {
            unsigned dst = (unsigned)__cvta_generic_to_shared(Wgs + (buf^1)*4224);
            const float* src = Wg + (c+1)*4224;
            for (int i = t; i < 1056; i += 256) cp_async16(dst + i*16, src + i*4);
            asm volatile("cp.async.commit_group;" ::: "memory");
            asm volatile("cp.async.wait_group 1;" ::: "memory");
        } else {
            asm volatile("cp.async.wait_group 0;" ::: "memory");
        }
        __syncthreads();
        const float* Wc = Wgs + buf*4224;
        const float* Ab = xcT + c*33*TM + tr*4;
        #pragma unroll 3
        for (int kk = 0; kk < 33; ++kk) {
            ulonglong2 p = *(const ulonglong2*)(Ab + kk*TM);      // rows tr*4..tr*4+3 (16B broadcast)
            float4 bv = *(const float4*)(Wc + kk*128 + tc*4);
            unsigned long long b0, b1, b2, b3;
            PACK2(b0, bv.x); PACK2(b1, bv.y); PACK2(b2, bv.z); PACK2(b3, bv.w);
            FMA2(acc[0][0], p.x, b0); FMA2(acc[0][1], p.x, b1); FMA2(acc[0][2], p.x, b2); FMA2(acc[0][3], p.x, b3);
            FMA2(acc[1][0], p.y, b0); FMA2(acc[1][1], p.y, b1); FMA2(acc[1][2], p.y, b2); FMA2(acc[1][3], p.y, b3);
        }
        __syncthreads();
        buf ^= 1;
    }

    size_t base = (size_t)(row0 + tr*4) * DD + tc*4;
    #pragma unroll
    for (int i = 0; i < 2; i++) {
        float lo[4], hi[4];
        #pragma unroll
        for (int j = 0; j < 4; j++) { UNPK(lo[j], hi[j], acc[i][j]); }
        *(float4*)(g_z + base + (size_t)(2*i)*DD)   = make_float4(lo[0], lo[1], lo[2], lo[3]);
        *(float4*)(g_z + base + (size_t)(2*i+1)*DD) = make_float4(hi[0], hi[1], hi[2], hi[3]);
    }

    // BN1 stats to global (sS/sQ writes ordered before the mainloop's syncs)
    if (t < TM) {
        int n = (int)((row0 + t) % NSEQ);
        atomicAdd(&g_s1[n], sS[t]);
        atomicAdd(&g_q1[n], sQ[t]);
    }
}

// ---------------- k_fin1: BN1 finalize + affine offset O1 (29 blocks) ----------------
__global__ void k_fin1(const float* __restrict__ Wg) {
    __shared__ float mi;
    int n = blockIdx.x, t = threadIdx.x;
    if (t == 0) {
        float cnt = (float)BB * (float)DCAT;
        float m = g_s1[n] / cnt;
        float v = g_q1[n] / cnt - m*m;
        float is = rsqrtf(v + EPS_BN);
        g_is1[n] = is; mi = m * is;
    }
    __syncthreads();
    float S = 0.f;
    #pragma unroll 4
    for (int k = 0; k < DCAT; k++) S += Wg[k*DD + t];
    g_O1[n*DD + t] = mi * S;
}

// ---------------- k_mix: u = prelu(corr @ z_bn + bg), in-place; BN2 stats ----------------
__global__ __launch_bounds__(256)
void k_mix(const float* __restrict__ corr, const float* __restrict__ bg,
           const float* __restrict__ ag)
{
    __shared__ float zs[NSEQ*DD];
    __shared__ float cs[NSEQ*NSEQ];
    __shared__ float i1s[NSEQ], ssum[NSEQ], ssq[NSEQ];
    int t = threadIdx.x, b = blockIdx.x;
    if (t < NSEQ) { i1s[t] = g_is1[t]; ssum[t] = 0.f; ssq[t] = 0.f; }
    __syncthreads();
    float* zg = g_z + (size_t)b * NSEQ * DD;
    for (int i = t; i < NSEQ*DD; i += 256) { int m = i >> 7; zs[i] = zg[i]*i1s[m] - g_O1[i]; }
    const float* cg = corr + (size_t)b * NSEQ * NSEQ;
    for (int i = t; i < NSEQ*NSEQ; i += 256) cs[i] = cg[i];
    __syncthreads();
    float agv = ag[0];
    if (t < 232) {
        int n = t >> 3, qd = t & 7, d0 = qd*16;
        const float* cr = cs + n*NSEQ;
        unsigned long long acc[8];
        #pragma unroll
        for (int j = 0; j < 8; j++) acc[j] = 0ull;
        #pragma unroll 1
        for (int m = 0; m < NSEQ; m++) {
            unsigned long long cd; PACK2(cd, cr[m]);
            const float* zr = zs + m*DD + d0;
            ulonglong2 z0 = *(const ulonglong2*)zr;
            ulonglong2 z1 = *(const ulonglong2*)(zr + 4);
            ulonglong2 z2 = *(const ulonglong2*)(zr + 8);
            ulonglong2 z3 = *(const ulonglong2*)(zr + 12);
            FMA2(acc[0], z0.x, cd); FMA2(acc[1], z0.y, cd);
            FMA2(acc[2], z1.x, cd); FMA2(acc[3], z1.y, cd);
            FMA2(acc[4], z2.x, cd); FMA2(acc[5], z2.y, cd);
            FMA2(acc[6], z3.x, cd); FMA2(acc[7], z3.y, cd);
        }
        float ls = 0.f, lq = 0.f;
        float* zo = zg + n*DD + d0;
        #pragma unroll
        for (int j = 0; j < 8; j++) {
            float lo, hi; UNPK(lo, hi, acc[j]);
            lo += bg[d0 + 2*j]; hi += bg[d0 + 2*j + 1];
            lo = (lo >= 0.f) ? lo : agv*lo;
            hi = (hi >= 0.f) ? hi : agv*hi;
            zo[2*j] = lo; zo[2*j+1] = hi;
            ls += lo + hi; lq += lo*lo + hi*hi;
        }
        atomicAdd(&ssum[n], ls);
        atomicAdd(&ssq[n], lq);
    }
    __syncthreads();
    if (t < NSEQ) { atomicAdd(&g_s2[t], ssum[t]); atomicAdd(&g_q2[t], ssq[t]); }
}

// ---------------- k_fin2: BN2 finalize + combined head vector v ----------------
__global__ void k_fin2(const float* __restrict__ cent, const float* __restrict__ hw) {
    __shared__ float nrm[4];
    int t = threadIdx.x;
    if (t < NSEQ) {
        float cnt = (float)BB * (float)DD;
        float m = g_s2[t] / cnt;
        float v = g_q2[t] / cnt - m*m;
        g_bn2m[t] = m; g_bn2i[t] = rsqrtf(v + EPS_BN);
    }
    if (t >= 32 && t < 36) {
        int h = t - 32; float s = 0.f;
        for (int d = 0; d < DD; d++) { float c = cent[h*DD + d]; s = fmaf(c, c, s); }
        nrm[h] = sqrtf(s) + 1e-8f;
    }
    __syncthreads();
    float v = 0.f;
    #pragma unroll
    for (int h = 0; h < 4; h++) v += hw[h] * cent[h*DD + t] / nrm[h];
    g_v[t] = v;
}

// ---------------- k_pool: BN2 apply + cosine-sim softmax pooling ----------------
__global__ __launch_bounds__(128)
void k_pool()
{
    __shared__ float xb[NSEQ*DD];
    __shared__ float vS[DD], m2[NSEQ], i2[NSEQ], aggS[32], CS[32];
    int t = threadIdx.x, b = blockIdx.x;
    if (t < NSEQ) { m2[t] = g_bn2m[t]; i2[t] = g_bn2i[t]; }
    vS[t] = g_v[t];
    __syncthreads();
    const float* ug = g_z + (size_t)b * NSEQ * DD;
    #pragma unroll 1
    for (int n = 0; n < NSEQ; n++) xb[n*DD + t] = (ug[n*DD + t] - m2[n]) * i2[n];
    __syncthreads();
    int w = t >> 5, l = t & 31;
    for (int n = w; n < NSEQ; n += 4) {
        float s2 = 0.f, sa = 0.f;
        #pragma unroll
        for (int dd = 0; dd < 4; dd++) {
            float x = xb[n*DD + l + dd*32];
            s2 = fmaf(x, x, s2);
            sa = fmaf(vS[l + dd*32], x, sa);
        }
        #pragma unroll
        for (int o = 16; o > 0; o >>= 1) {
            s2 += __shfl_down_sync(0xffffffffu, s2, o);
            sa += __shfl_down_sync(0xffffffffu, sa, o);
        }
        if (l == 0) aggS[n] = sa / (sqrtf(s2) + 1e-8f);
    }
    __syncthreads();
    if (w == 0) {
        float a = (l < NSEQ) ? aggS[l] : -1e30f;
        float mx = a;
        #pragma unroll
        for (int o = 16; o > 0; o >>= 1) mx = fmaxf(mx, __shfl_xor_sync(0xffffffffu, mx, o));
        float e = (l < NSEQ) ? expf(a - mx) : 0.f;
        float s = e;
        #pragma unroll
        for (int o = 16; o > 0; o >>= 1) s += __shfl_xor_sync(0xffffffffu, s, o);
        if (l < NSEQ) CS[l] = e / s;
    }
    __syncthreads();
    float p = 0.f;
    #pragma unroll 1
    for (int n = 0; n < NSEQ; n++) p = fmaf(CS[n], xb[n*DD + t], p);
    g_pool[(size_t)b*DD + t] = p;
}

// ---------------- k_projp: p = pooled @ Wp + bp; BN3 stats ----------------
__global__ __launch_bounds__(256)
void k_projp(const float* __restrict__ Wp, const float* __restrict__ bp)
{
    __shared__ float xs[64*DD];
    __shared__ float ss[DD], sq[DD];
    int t = threadIdx.x;
    size_t row0 = (size_t)blockIdx.x * 64;
    for (int i = t; i < 64*DD; i += 256) xs[i] = g_pool[row0*DD + i];
    if (t < DD) { ss[t] = 0.f; sq[t] = 0.f; }
    __syncthreads();
    int tc = t & 31, tr = t >> 5;
    float acc[8][4];
    #pragma unroll
    for (int i = 0; i < 8; i++)
        #pragma unroll
        for (int j = 0; j < 4; j++) acc[i][j] = 0.f;
    for (int k = 0; k < DD; k++) {
        float4 bv = *(const float4*)(Wp + k*DD + tc*4);
        #pragma unroll
        for (int i = 0; i < 8; i++) {
            float a = xs[(tr*8 + i)*DD + k];
            acc[i][0] = fmaf(a, bv.x, acc[i][0]);
            acc[i][1] = fmaf(a, bv.y, acc[i][1]);
            acc[i][2] = fmaf(a, bv.z, acc[i][2]);
            acc[i][3] = fmaf(a, bv.w, acc[i][3]);
        }
    }
    float4 bpv = *(const float4*)(bp + tc*4);
    float csum[4] = {0,0,0,0}, cq[4] = {0,0,0,0};
    #pragma unroll
    for (int i = 0; i < 8; i++) {
        float o0 = acc[i][0] + bpv.x, o1 = acc[i][1] + bpv.y;
        float o2 = acc[i][2] + bpv.z, o3 = acc[i][3] + bpv.w;
        *(float4*)(g_p + (row0 + tr*8 + i)*DD + tc*4) = make_float4(o0, o1, o2, o3);
        csum[0]+=o0; csum[1]+=o1; csum[2]+=o2; csum[3]+=o3;
        cq[0]=fmaf(o0,o0,cq[0]); cq[1]=fmaf(o1,o1,cq[1]); cq[2]=fmaf(o2,o2,cq[2]); cq[3]=fmaf(o3,o3,cq[3]);
    }
    #pragma unroll
    for (int j = 0; j < 4; j++) { atomicAdd(&ss[tc*4+j], csum[j]); atomicAdd(&sq[tc*4+j], cq[j]); }
    __syncthreads();
    if (t < DD) { atomicAdd(&g_s3[t], ss[t]); atomicAdd(&g_q3[t], sq[t]); }
}

__global__ void k_fin3() {
    int t = threadIdx.x;
    if (t < DD) {
        float m = g_s3[t] / (float)BB;
        float v = g_q3[t] / (float)BB - m*m;
        g_bn3m[t] = m; g_bn3i[t] = rsqrtf(v + EPS_BN);
    }
}

// ---------------- k_mlp ----------------
__global__ __launch_bounds__(128)
void k_mlp(const float* __restrict__ Wm1, const float* __restrict__ bm1,
           const float* __restrict__ am, const float* __restrict__ Wm2,
           const float* __restrict__ bm2, float* __restrict__ out)
{
    __shared__ float xbn[16*DD];
    __shared__ float sg[16*DD];
    int t = threadIdx.x;
    size_t row0 = (size_t)blockIdx.x * 16;
    for (int i = t; i < 16*DD; i += 128) {
        int k = i & 127;
        xbn[i] = (g_p[row0*DD + i] - g_bn3m[k]) * g_bn3i[k];
    }
    __syncthreads();
    float amv = am[0], w2 = Wm2[t], b1v = bm1[t];
    float acc[16];
    #pragma unroll
    for (int r = 0; r < 16; r++) acc[r] = b1v;
    #pragma unroll 4
    for (int k = 0; k < DD; k++) {
        float wv = Wm1[k*DD + t];
        #pragma unroll
        for (int r = 0; r < 16; r++) acc[r] = fmaf(xbn[r*DD + k], wv, acc[r]);
    }
    #pragma unroll
    for (int r = 0; r < 16; r++) {
        float h = acc[r];
        h = (h >= 0.f) ? h : amv*h;
        sg[r*DD + t] = h * w2;
    }
    __syncthreads();
    int w = t >> 5, l = t & 31;
    float b2 = bm2[0];
    #pragma unroll
    for (int rr = 0; rr < 4; rr++) {
        int r = w*4 + rr;
        float s = sg[r*DD + l] + sg[r*DD + l + 32] + sg[r*DD + l + 64] + sg[r*DD + l + 96];
        #pragma unroll
        for (int o = 16; o > 0; o >>= 1) s += __shfl_down_sync(0xffffffffu, s, o);
        if (l == 0) out[row0 + r] = 1.f / (1.f + expf(-(s + b2)));
    }
}

// ---------------- launch ----------------
extern "C" void kernel_launch(void* const* d_in, const int* in_sizes, int n_in,
                              void* d_out, int out_size) {
    const float* X    = (const float*)d_in[0];
    const float* corr = (const float*)d_in[1];
    const float* w1   = (const float*)d_in[2];
    const float* b1   = (const float*)d_in[3];
    const float* w2   = (const float*)d_in[4];
    const float* b2   = (const float*)d_in[5];
    const float* w3   = (const float*)d_in[6];
    const float* b3   = (const float*)d_in[7];
    const float* ac   = (const float*)d_in[8];
    const float* Wg   = (const float*)d_in[9];
    const float* bg   = (const float*)d_in[10];
    const float* ag   = (const float*)d_in[11];
    const float* cent = (const float*)d_in[12];
    const float* hw   = (const float*)d_in[13];
    const float* Wp   = (const float*)d_in[14];
    const float* bp   = (const float*)d_in[15];
    const float* Wm1  = (const float*)d_in[16];
    const float* bm1  = (const float*)d_in[17];
    const float* am   = (const float*)d_in[18];
    const float* Wm2  = (const float*)d_in[19];
    const float* bm2  = (const float*)d_in[20];
    float* out = (float*)d_out;

    cudaFuncSetAttribute(k_gemm, cudaFuncAttributeMaxDynamicSharedMemorySize, GEMM_SMEM);

    k_reset<<<1, 128>>>();
    k_gemm<<<NROWS/TM, 256, GEMM_SMEM>>>(X, Wg, w1, b1, w2, b2, w3, b3, ac);
    k_fin1<<<NSEQ, 128>>>(Wg);
    k_mix<<<BB, 256>>>(corr, bg, ag);
    k_fin2<<<1, 128>>>(cent, hw);
    k_pool<<<BB, 128>>>();
    k_projp<<<BB/64, 256>>>(Wp, bp);
    k_fin3<<<1, 128>>>();
    k_mlp<<<BB/16, 128>>>(Wm1, bm1, am, Wm2, bm2, out);
}

// round 12
// speedup vs baseline: 1.4039x; 1.2597x over previous
#include <cuda_runtime.h>
#include <cuda_bf16.h>
#include <math.h>
#include <stdint.h>

#define BB 8192
#define NSEQ 29
#define FF 147
#define DD 128
#define DCAT 429
#define NROWS (BB*NSEQ)
#define TM 32
#define EPS_BN 1e-5f

// ---------------- scratch ----------------
__device__ float g_z[(size_t)NROWS * DD];   // raw z = xp@Wg, then overwritten in-place by u
__device__ float g_pool[BB * DD];
__device__ float g_p[BB * DD];
__device__ float g_s1[NSEQ], g_q1[NSEQ];
__device__ float g_is1[NSEQ], g_m1[NSEQ];
__device__ float g_S[DD];                   // colsum of Wg
__device__ float g_s2[NSEQ], g_q2[NSEQ];
__device__ float g_bn2m[NSEQ], g_bn2i[NSEQ];
__device__ float g_v[DD];
__device__ float g_s3[DD], g_q3[DD];
__device__ float g_bn3m[DD], g_bn3i[DD];

#define FMA2(d, a, b) asm("fma.rn.f32x2 %0, %1, %2, %0;" : "+l"(d) : "l"(a), "l"(b))
#define PACK2(d, f)   asm("mov.b64 %0, {%1, %1};" : "=l"(d) : "r"(__float_as_uint(f)))
#define UNPK(lo, hi, p) { unsigned _l,_h; asm("mov.b64 {%0,%1}, %2;":"=r"(_l),"=r"(_h):"l"(p)); lo=__uint_as_float(_l); hi=__uint_as_float(_h); }

__device__ __forceinline__ void cp_async16(unsigned saddr, const void* g) {
    asm volatile("cp.async.cg.shared.global [%0], [%1], 16;" :: "r"(saddr), "l"(g) : "memory");
}

__device__ __forceinline__ float conv_val(const float* __restrict__ xr, const float* __restrict__ w, int k) {
    float v;
    if (k < 145) {
        v = fmaf(xr[k], w[0], fmaf(xr[k+1], w[1], fmaf(xr[k+2], w[2], w[15])));
    } else if (k < 288) {
        int j = k - 145; v = w[16];
        #pragma unroll
        for (int u = 0; u < 5; u++) v = fmaf(xr[j+u], w[3+u], v);
    } else {
        int j = k - 288; v = w[17];
        #pragma unroll
        for (int u = 0; u < 7; u++) v = fmaf(xr[j+u], w[8+u], v);
    }
    return v;
}

__device__ __forceinline__ void load_ws(float* ws, const float* w1, const float* b1,
    const float* w2, const float* b2, const float* w3, const float* b3, const float* ac) {
    ws[0]=w1[0]; ws[1]=w1[1]; ws[2]=w1[2];
    ws[3]=w2[0]; ws[4]=w2[1]; ws[5]=w2[2]; ws[6]=w2[3]; ws[7]=w2[4];
    ws[8]=w3[0]; ws[9]=w3[1]; ws[10]=w3[2]; ws[11]=w3[3]; ws[12]=w3[4]; ws[13]=w3[5]; ws[14]=w3[6];
    ws[15]=b1[0]; ws[16]=b2[0]; ws[17]=b3[0]; ws[18]=ac[0];
}

// ---------------- k_reset ----------------
__global__ void k_reset() {
    int t = threadIdx.x;
    if (t < NSEQ) { g_s1[t]=0.f; g_q1[t]=0.f; g_s2[t]=0.f; g_q2[t]=0.f; }
    if (t < DD)   { g_s3[t]=0.f; g_q3[t]=0.f; }
}

// ---------------- k_gemm: conv+prelu (+BN1 stats) -> raw z = xp @ Wg (f32x2) ----------------
#define GEMM_SMEM ((TM*149 + DCAT*TM + 2*33*128) * 4)

__global__ __launch_bounds__(256, 2)
void k_gemm(const float* __restrict__ X, const float* __restrict__ Wg,
            const float* w1, const float* b1, const float* w2, const float* b2,
            const float* w3, const float* b3, const float* ac)
{
    extern __shared__ float sm[];
    float* Xs  = sm;                  // [32][149]
    float* xcT = Xs + TM*149;         // [429][32], k-major
    float* Wgs = xcT + DCAT*TM;       // 2 x [33][128]
    __shared__ float ws[20];
    __shared__ float sS[TM], sQ[TM];

    int t = threadIdx.x;
    long row0 = (long)blockIdx.x * TM;

    { // prefetch Wg chunk 0
        unsigned dst = (unsigned)__cvta_generic_to_shared(Wgs);
        for (int i = t; i < 1056; i += 256) cp_async16(dst + i*16, Wg + i*4);
        asm volatile("cp.async.commit_group;" ::: "memory");
    }
    const float* Xb = X + row0 * FF;
    for (int e = t; e < TM*FF; e += 256) { int rr = e/FF, j = e - rr*FF; Xs[rr*149+j] = Xb[e]; }
    if (t == 0) load_ws(ws, w1,b1,w2,b2,w3,b3,ac);
    if (t < TM) { sS[t] = 0.f; sQ[t] = 0.f; }
    __syncthreads();

    float a = ws[18];
    int rr = t & 31;
    {
        const float* xr = Xs + rr*149;
        float ls = 0.f, lq = 0.f;
        for (int e = t; e < DCAT*TM; e += 256) {
            int k = e >> 5;
            float v = conv_val(xr, ws, k);
            v = (v >= 0.f) ? v : a*v;
            xcT[k*TM + rr] = v;
            ls += v; lq = fmaf(v, v, lq);
        }
        atomicAdd(&sS[rr], ls);
        atomicAdd(&sQ[rr], lq);
    }

    int tc = t & 31, tr = t >> 5;
    unsigned long long acc[2][4];
    #pragma unroll
    for (int i = 0; i < 2; i++)
        #pragma unroll
        for (int j = 0; j < 4; j++) acc[i][j] = 0ull;

    int buf = 0;
    for (int c = 0; c < 13; ++c) {
        if (c < 12) {
            unsigned dst = (unsigned)__cvta_generic_to_shared(Wgs + (buf^1)*4224);
            const float* src = Wg + (c+1)*4224;
            for (int i = t; i < 1056; i += 256) cp_async16(dst + i*16, src + i*4);
            asm volatile("cp.async.commit_group;" ::: "memory");
            asm volatile("cp.async.wait_group 1;" ::: "memory");
        } else {
            asm volatile("cp.async.wait_group 0;" ::: "memory");
        }
        __syncthreads();
        const float* Wc = Wgs + buf*4224;
        const float* Ab = xcT + c*33*TM + tr*4;
        #pragma unroll 3
        for (int kk = 0; kk < 33; ++kk) {
            ulonglong2 p = *(const ulonglong2*)(Ab + kk*TM);
            float4 bv = *(const float4*)(Wc + kk*128 + tc*4);
            unsigned long long b0, b1, b2, b3;
            PACK2(b0, bv.x); PACK2(b1, bv.y); PACK2(b2, bv.z); PACK2(b3, bv.w);
            FMA2(acc[0][0], p.x, b0); FMA2(acc[0][1], p.x, b1); FMA2(acc[0][2], p.x, b2); FMA2(acc[0][3], p.x, b3);
            FMA2(acc[1][0], p.y, b0); FMA2(acc[1][1], p.y, b1); FMA2(acc[1][2], p.y, b2); FMA2(acc[1][3], p.y, b3);
        }
        __syncthreads();
        buf ^= 1;
    }

    size_t base = (size_t)(row0 + tr*4) * DD + tc*4;
    #pragma unroll
    for (int i = 0; i < 2; i++) {
        float lo[4], hi[4];
        #pragma unroll
        for (int j = 0; j < 4; j++) { UNPK(lo[j], hi[j], acc[i][j]); }
        *(float4*)(g_z + base + (size_t)(2*i)*DD)   = make_float4(lo[0], lo[1], lo[2], lo[3]);
        *(float4*)(g_z + base + (size_t)(2*i+1)*DD) = make_float4(hi[0], hi[1], hi[2], hi[3]);
    }

    if (t < TM) {
        int n = (int)((row0 + t) % NSEQ);
        atomicAdd(&g_s1[n], sS[t]);
        atomicAdd(&g_q1[n], sQ[t]);
    }
}

// ---------------- k_fin1: BN1 finalize + colsum S (1 block, 256 threads) ----------------
__global__ void k_fin1(const float* __restrict__ Wg) {
    __shared__ float Ssh[DD];
    int t = threadIdx.x;
    if (t < NSEQ) {
        float cnt = (float)BB * (float)DCAT;
        float m = g_s1[t] / cnt;
        float v = g_q1[t] / cnt - m*m;
        g_is1[t] = rsqrtf(v + EPS_BN);
        g_m1[t]  = m;
    }
    int d = t & 127, h = t >> 7;        // two halves split the k-sum
    float S = 0.f;
    #pragma unroll 8
    for (int k = h; k < DCAT; k += 2) S += Wg[k*DD + d];
    if (h == 1) Ssh[d] = S;
    __syncthreads();
    if (h == 0) g_S[d] = S + Ssh[d];
}

// ---------------- k_mix: u = prelu(corr @ z_bn + bg) via rank-1 BN fold; BN2 stats ----------
// block = 128 threads = 2 batches x 64 threads; each thread owns a d-pair.
__global__ __launch_bounds__(128)
void k_mix(const float* __restrict__ corr, const float* __restrict__ bg,
           const float* __restrict__ ag)
{
    __shared__ float2 cs[2*NSEQ*32];        // c'[n][m] duplicated as f32x2, m padded to 32
    __shared__ float qs[2*32];
    __shared__ float ssum[2*32], ssq[2*32];
    __shared__ float i1s[32], m1s[32];

    int t = threadIdx.x;
    int lb = t >> 6, lt = t & 63;
    int b = blockIdx.x * 2 + lb;

    // issue z column loads early (raw z, registers)
    unsigned long long zz[32];
    const float* zb = g_z + (size_t)b * NSEQ * DD + 2*lt;
    #pragma unroll
    for (int m = 0; m < NSEQ; m++) zz[m] = *(const unsigned long long*)(zb + m*DD);
    zz[29] = 0ull; zz[30] = 0ull; zz[31] = 0ull;

    if (t < NSEQ) { i1s[t] = g_is1[t]; m1s[t] = g_m1[t]; }
    if (t < 64) { ssum[t] = 0.f; ssq[t] = 0.f; }
    __syncthreads();

    // build c' = corr * i1 (dup-packed), zero-padded to m=32
    {
        const float* cgb = corr + (size_t)b * NSEQ * NSEQ;
        for (int idx = lt; idx < NSEQ*32; idx += 64) {
            int n = idx >> 5, m = idx & 31;
            float v = (m < NSEQ) ? cgb[n*NSEQ + m] * i1s[m] : 0.f;
            cs[(lb*NSEQ + n)*32 + m] = make_float2(v, v);
        }
    }
    __syncthreads();

    // q[n] = sum_m c'[n][m] * m1[m]
    if (lt < NSEQ) {
        float q = 0.f;
        #pragma unroll
        for (int m = 0; m < NSEQ; m++) q = fmaf(cs[(lb*NSEQ + lt)*32 + m].x, m1s[m], q);
        qs[lb*32 + lt] = q;
    }
    __syncthreads();

    float2 S2 = *(const float2*)(g_S + 2*lt);
    float2 bg2 = *(const float2*)(bg + 2*lt);
    float agv = ag[0];
    float* zg = g_z + (size_t)b * NSEQ * DD + 2*lt;
    int lane = t & 31;

    #pragma unroll 1
    for (int n = 0; n < NSEQ; n++) {
        const ulonglong2* cr = (const ulonglong2*)&cs[(lb*NSEQ + n)*32];
        unsigned long long acc = 0ull;
        #pragma unroll
        for (int ch = 0; ch < 16; ch++) {
            ulonglong2 cc = cr[ch];
            FMA2(acc, zz[2*ch],   cc.x);
            FMA2(acc, zz[2*ch+1], cc.y);
        }
        float u0, u1; UNPK(u0, u1, acc);
        float qn = qs[lb*32 + n];
        u0 = u0 - S2.x*qn + bg2.x;
        u1 = u1 - S2.y*qn + bg2.y;
        u0 = (u0 >= 0.f) ? u0 : agv*u0;
        u1 = (u1 >= 0.f) ? u1 : agv*u1;
        *(float2*)(zg + n*DD) = make_float2(u0, u1);
        float su = u0 + u1;
        float s2v = u0*u0 + u1*u1;
        #pragma unroll
        for (int o = 16; o > 0; o >>= 1) {
            su  += __shfl_down_sync(0xffffffffu, su,  o);
            s2v += __shfl_down_sync(0xffffffffu, s2v, o);
        }
        if (lane == 0) {
            atomicAdd(&ssum[lb*32 + n], su);
            atomicAdd(&ssq[lb*32 + n], s2v);
        }
    }
    __syncthreads();
    if (t < 2*NSEQ) {
        int lb2 = t / NSEQ, n = t - lb2*NSEQ;
        atomicAdd(&g_s2[n], ssum[lb2*32 + n]);
        atomicAdd(&g_q2[n], ssq[lb2*32 + n]);
    }
}

// ---------------- k_fin2: BN2 finalize + combined head vector v ----------------
__global__ void k_fin2(const float* __restrict__ cent, const float* __restrict__ hw) {
    __shared__ float nrm[4];
    int t = threadIdx.x;
    if (t < NSEQ) {
        float cnt = (float)BB * (float)DD;
        float m = g_s2[t] / cnt;
        float v = g_q2[t] / cnt - m*m;
        g_bn2m[t] = m; g_bn2i[t] = rsqrtf(v + EPS_BN);
    }
    if (t >= 32 && t < 36) {
        int h = t - 32; float s = 0.f;
        for (int d = 0; d < DD; d++) { float c = cent[h*DD + d]; s = fmaf(c, c, s); }
        nrm[h] = sqrtf(s) + 1e-8f;
    }
    __syncthreads();
    float v = 0.f;
    #pragma unroll
    for (int h = 0; h < 4; h++) v += hw[h] * cent[h*DD + t] / nrm[h];
    g_v[t] = v;
}

// ---------------- k_pool: BN2 apply + cosine-sim softmax pooling ----------------
__global__ __launch_bounds__(128)
void k_pool()
{
    __shared__ float xb[NSEQ*DD];
    __shared__ float vS[DD], m2[NSEQ], i2[NSEQ], aggS[32], CS[32];
    int t = threadIdx.x, b = blockIdx.x;
    if (t < NSEQ) { m2[t] = g_bn2m[t]; i2[t] = g_bn2i[t]; }
    vS[t] = g_v[t];
    __syncthreads();
    const float* ug = g_z + (size_t)b * NSEQ * DD;
    #pragma unroll 1
    for (int n = 0; n < NSEQ; n++) xb[n*DD + t] = (ug[n*DD + t] - m2[n]) * i2[n];
    __syncthreads();
    int w = t >> 5, l = t & 31;
    for (int n = w; n < NSEQ; n += 4) {
        float s2 = 0.f, sa = 0.f;
        #pragma unroll
        for (int dd = 0; dd < 4; dd++) {
            float x = xb[n*DD + l + dd*32];
            s2 = fmaf(x, x, s2);
            sa = fmaf(vS[l + dd*32], x, sa);
        }
        #pragma unroll
        for (int o = 16; o > 0; o >>= 1) {
            s2 += __shfl_down_sync(0xffffffffu, s2, o);
            sa += __shfl_down_sync(0xffffffffu, sa, o);
        }
        if (l == 0) aggS[n] = sa / (sqrtf(s2) + 1e-8f);
    }
    __syncthreads();
    if (w == 0) {
        float a = (l < NSEQ) ? aggS[l] : -1e30f;
        float mx = a;
        #pragma unroll
        for (int o = 16; o > 0; o >>= 1) mx = fmaxf(mx, __shfl_xor_sync(0xffffffffu, mx, o));
        float e = (l < NSEQ) ? expf(a - mx) : 0.f;
        float s = e;
        #pragma unroll
        for (int o = 16; o > 0; o >>= 1) s += __shfl_xor_sync(0xffffffffu, s, o);
        if (l < NSEQ) CS[l] = e / s;
    }
    __syncthreads();
    float p = 0.f;
    #pragma unroll 1
    for (int n = 0; n < NSEQ; n++) p = fmaf(CS[n], xb[n*DD + t], p);
    g_pool[(size_t)b*DD + t] = p;
}

// ---------------- k_projp: p = pooled @ Wp + bp; BN3 stats ----------------
__global__ __launch_bounds__(256)
void k_projp(const float* __restrict__ Wp, const float* __restrict__ bp)
{
    __shared__ float xs[64*DD];
    __shared__ float ss[DD], sq[DD];
    int t = threadIdx.x;
    size_t row0 = (size_t)blockIdx.x * 64;
    for (int i = t; i < 64*DD; i += 256) xs[i] = g_pool[row0*DD + i];
    if (t < DD) { ss[t] = 0.f; sq[t] = 0.f; }
    __syncthreads();
    int tc = t & 31, tr = t >> 5;
    float acc[8][4];
    #pragma unroll
    for (int i = 0; i < 8; i++)
        #pragma unroll
        for (int j = 0; j < 4; j++) acc[i][j] = 0.f;
    for (int k = 0; k < DD; k++) {
        float4 bv = *(const float4*)(Wp + k*DD + tc*4);
        #pragma unroll
        for (int i = 0; i < 8; i++) {
            float a = xs[(tr*8 + i)*DD + k];
            acc[i][0] = fmaf(a, bv.x, acc[i][0]);
            acc[i][1] = fmaf(a, bv.y, acc[i][1]);
            acc[i][2] = fmaf(a, bv.z, acc[i][2]);
            acc[i][3] = fmaf(a, bv.w, acc[i][3]);
        }
    }
    float4 bpv = *(const float4*)(bp + tc*4);
    float csum[4] = {0,0,0,0}, cq[4] = {0,0,0,0};
    #pragma unroll
    for (int i = 0; i < 8; i++) {
        float o0 = acc[i][0] + bpv.x, o1 = acc[i][1] + bpv.y;
        float o2 = acc[i][2] + bpv.z, o3 = acc[i][3] + bpv.w;
        *(float4*)(g_p + (row0 + tr*8 + i)*DD + tc*4) = make_float4(o0, o1, o2, o3);
        csum[0]+=o0; csum[1]+=o1; csum[2]+=o2; csum[3]+=o3;
        cq[0]=fmaf(o0,o0,cq[0]); cq[1]=fmaf(o1,o1,cq[1]); cq[2]=fmaf(o2,o2,cq[2]); cq[3]=fmaf(o3,o3,cq[3]);
    }
    #pragma unroll
    for (int j = 0; j < 4; j++) { atomicAdd(&ss[tc*4+j], csum[j]); atomicAdd(&sq[tc*4+j], cq[j]); }
    __syncthreads();
    if (t < DD) { atomicAdd(&g_s3[t], ss[t]); atomicAdd(&g_q3[t], sq[t]); }
}

__global__ void k_fin3() {
    int t = threadIdx.x;
    if (t < DD) {
        float m = g_s3[t] / (float)BB;
        float v = g_q3[t] / (float)BB - m*m;
        g_bn3m[t] = m; g_bn3i[t] = rsqrtf(v + EPS_BN);
    }
}

// ---------------- k_mlp ----------------
__global__ __launch_bounds__(128)
void k_mlp(const float* __restrict__ Wm1, const float* __restrict__ bm1,
           const float* __restrict__ am, const float* __restrict__ Wm2,
           const float* __restrict__ bm2, float* __restrict__ out)
{
    __shared__ float xbn[16*DD];
    __shared__ float sg[16*DD];
    int t = threadIdx.x;
    size_t row0 = (size_t)blockIdx.x * 16;
    for (int i = t; i < 16*DD; i += 128) {
        int k = i & 127;
        xbn[i] = (g_p[row0*DD + i] - g_bn3m[k]) * g_bn3i[k];
    }
    __syncthreads();
    float amv = am[0], w2 = Wm2[t], b1v = bm1[t];
    float acc[16];
    #pragma unroll
    for (int r = 0; r < 16; r++) acc[r] = b1v;
    #pragma unroll 4
    for (int k = 0; k < DD; k++) {
        float wv = Wm1[k*DD + t];
        #pragma unroll
        for (int r = 0; r < 16; r++) acc[r] = fmaf(xbn[r*DD + k], wv, acc[r]);
    }
    #pragma unroll
    for (int r = 0; r < 16; r++) {
        float h = acc[r];
        h = (h >= 0.f) ? h : amv*h;
        sg[r*DD + t] = h * w2;
    }
    __syncthreads();
    int w = t >> 5, l = t & 31;
    float b2 = bm2[0];
    #pragma unroll
    for (int rr = 0; rr < 4; rr++) {
        int r = w*4 + rr;
        float s = sg[r*DD + l] + sg[r*DD + l + 32] + sg[r*DD + l + 64] + sg[r*DD + l + 96];
        #pragma unroll
        for (int o = 16; o > 0; o >>= 1) s += __shfl_down_sync(0xffffffffu, s, o);
        if (l == 0) out[row0 + r] = 1.f / (1.f + expf(-(s + b2)));
    }
}

// ---------------- launch ----------------
extern "C" void kernel_launch(void* const* d_in, const int* in_sizes, int n_in,
                              void* d_out, int out_size) {
    const float* X    = (const float*)d_in[0];
    const float* corr = (const float*)d_in[1];
    const float* w1   = (const float*)d_in[2];
    const float* b1   = (const float*)d_in[3];
    const float* w2   = (const float*)d_in[4];
    const float* b2   = (const float*)d_in[5];
    const float* w3   = (const float*)d_in[6];
    const float* b3   = (const float*)d_in[7];
    const float* ac   = (const float*)d_in[8];
    const float* Wg   = (const float*)d_in[9];
    const float* bg   = (const float*)d_in[10];
    const float* ag   = (const float*)d_in[11];
    const float* cent = (const float*)d_in[12];
    const float* hw   = (const float*)d_in[13];
    const float* Wp   = (const float*)d_in[14];
    const float* bp   = (const float*)d_in[15];
    const float* Wm1  = (const float*)d_in[16];
    const float* bm1  = (const float*)d_in[17];
    const float* am   = (const float*)d_in[18];
    const float* Wm2  = (const float*)d_in[19];
    const float* bm2  = (const float*)d_in[20];
    float* out = (float*)d_out;

    cudaFuncSetAttribute(k_gemm, cudaFuncAttributeMaxDynamicSharedMemorySize, GEMM_SMEM);

    k_reset<<<1, 128>>>();
    k_gemm<<<NROWS/TM, 256, GEMM_SMEM>>>(X, Wg, w1, b1, w2, b2, w3, b3, ac);
    k_fin1<<<1, 256>>>(Wg);
    k_mix<<<BB/2, 128>>>(corr, bg, ag);
    k_fin2<<<1, 128>>>(cent, hw);
    k_pool<<<BB, 128>>>();
    k_projp<<<BB/64, 256>>>(Wp, bp);
    k_fin3<<<1, 128>>>();
    k_mlp<<<BB/16, 128>>>(Wm1, bm1, am, Wm2, bm2, out);
}

// round 13
// speedup vs baseline: 1.4605x; 1.0403x over previous
#include <cuda_runtime.h>
#include <cuda_bf16.h>
#include <math.h>
#include <stdint.h>

#define BB 8192
#define NSEQ 29
#define FF 147
#define DD 128
#define DCAT 429
#define NROWS (BB*NSEQ)
#define TM 32
#define EPS_BN 1e-5f

// ---------------- scratch ----------------
__device__ float g_z[(size_t)NROWS * DD];   // raw z = xp@Wg, then overwritten in-place by u
__device__ float g_pool[BB * DD];
__device__ float g_p[BB * DD];
__device__ float g_s1[NSEQ], g_q1[NSEQ];
__device__ float g_is1[NSEQ], g_m1[NSEQ];
__device__ float g_S[DD];                   // colsum of Wg
__device__ float g_s2[NSEQ], g_q2[NSEQ];
__device__ float g_bn2m[NSEQ], g_bn2i[NSEQ];
__device__ float g_v[DD];
__device__ float g_s3[DD], g_q3[DD];
__device__ float g_bn3m[DD], g_bn3i[DD];

#define FMA2(d, a, b) asm("fma.rn.f32x2 %0, %1, %2, %0;" : "+l"(d) : "l"(a), "l"(b))
#define PACK2(d, f)   asm("mov.b64 %0, {%1, %1};" : "=l"(d) : "r"(__float_as_uint(f)))
#define UNPK(lo, hi, p) { unsigned _l,_h; asm("mov.b64 {%0,%1}, %2;":"=r"(_l),"=r"(_h):"l"(p)); lo=__uint_as_float(_l); hi=__uint_as_float(_h); }

__device__ __forceinline__ void cp_async16(unsigned saddr, const void* g) {
    asm volatile("cp.async.cg.shared.global [%0], [%1], 16;" :: "r"(saddr), "l"(g) : "memory");
}

__device__ __forceinline__ float conv_val(const float* __restrict__ xr, const float* __restrict__ w, int k) {
    float v;
    if (k < 145) {
        v = fmaf(xr[k], w[0], fmaf(xr[k+1], w[1], fmaf(xr[k+2], w[2], w[15])));
    } else if (k < 288) {
        int j = k - 145; v = w[16];
        #pragma unroll
        for (int u = 0; u < 5; u++) v = fmaf(xr[j+u], w[3+u], v);
    } else {
        int j = k - 288; v = w[17];
        #pragma unroll
        for (int u = 0; u < 7; u++) v = fmaf(xr[j+u], w[8+u], v);
    }
    return v;
}

__device__ __forceinline__ void load_ws(float* ws, const float* w1, const float* b1,
    const float* w2, const float* b2, const float* w3, const float* b3, const float* ac) {
    ws[0]=w1[0]; ws[1]=w1[1]; ws[2]=w1[2];
    ws[3]=w2[0]; ws[4]=w2[1]; ws[5]=w2[2]; ws[6]=w2[3]; ws[7]=w2[4];
    ws[8]=w3[0]; ws[9]=w3[1]; ws[10]=w3[2]; ws[11]=w3[3]; ws[12]=w3[4]; ws[13]=w3[5]; ws[14]=w3[6];
    ws[15]=b1[0]; ws[16]=b2[0]; ws[17]=b3[0]; ws[18]=ac[0];
}

// ---------------- k_reset ----------------
__global__ void k_reset() {
    int t = threadIdx.x;
    if (t < NSEQ) { g_s1[t]=0.f; g_q1[t]=0.f; g_s2[t]=0.f; g_q2[t]=0.f; }
    if (t < DD)   { g_s3[t]=0.f; g_q3[t]=0.f; }
}

// ---------------- k_gemm: conv+prelu (+BN1 stats) -> raw z = xp @ Wg (f32x2) ----------------
#define GEMM_SMEM ((TM*149 + DCAT*TM + 2*33*128) * 4)

__global__ __launch_bounds__(256, 2)
void k_gemm(const float* __restrict__ X, const float* __restrict__ Wg,
            const float* w1, const float* b1, const float* w2, const float* b2,
            const float* w3, const float* b3, const float* ac)
{
    extern __shared__ float sm[];
    float* Xs  = sm;                  // [32][149]
    float* xcT = Xs + TM*149;         // [429][32], k-major
    float* Wgs = xcT + DCAT*TM;       // 2 x [33][128]
    __shared__ float ws[20];
    __shared__ float sS[TM], sQ[TM];

    int t = threadIdx.x;
    long row0 = (long)blockIdx.x * TM;

    { // prefetch Wg chunk 0
        unsigned dst = (unsigned)__cvta_generic_to_shared(Wgs);
        for (int i = t; i < 1056; i += 256) cp_async16(dst + i*16, Wg + i*4);
        asm volatile("cp.async.commit_group;" ::: "memory");
    }
    const float* Xb = X + row0 * FF;
    for (int e = t; e < TM*FF; e += 256) { int rr = e/FF, j = e - rr*FF; Xs[rr*149+j] = Xb[e]; }
    if (t == 0) load_ws(ws, w1,b1,w2,b2,w3,b3,ac);
    if (t < TM) { sS[t] = 0.f; sQ[t] = 0.f; }
    __syncthreads();

    float a = ws[18];
    int rr = t & 31;
    {
        const float* xr = Xs + rr*149;
        float ls = 0.f, lq = 0.f;
        for (int e = t; e < DCAT*TM; e += 256) {
            int k = e >> 5;
            float v = conv_val(xr, ws, k);
            v = (v >= 0.f) ? v : a*v;
            xcT[k*TM + rr] = v;
            ls += v; lq = fmaf(v, v, lq);
        }
        atomicAdd(&sS[rr], ls);
        atomicAdd(&sQ[rr], lq);
    }

    // thread tile: 8 rows (tr) x 2 cols (tc) => A natural f32x2 pairs, B needs only 2 dups
    int tc = t & 63, tr = t >> 6;
    unsigned long long acc[4][2];
    #pragma unroll
    for (int i = 0; i < 4; i++) { acc[i][0] = 0ull; acc[i][1] = 0ull; }

    int buf = 0;
    for (int c = 0; c < 13; ++c) {
        if (c < 12) {
            unsigned dst = (unsigned)__cvta_generic_to_shared(Wgs + (buf^1)*4224);
            const float* src = Wg + (c+1)*4224;
            for (int i = t; i < 1056; i += 256) cp_async16(dst + i*16, src + i*4);
            asm volatile("cp.async.commit_group;" ::: "memory");
            asm volatile("cp.async.wait_group 1;" ::: "memory");
        } else {
            asm volatile("cp.async.wait_group 0;" ::: "memory");
        }
        __syncthreads();
        const float* Wc = Wgs + buf*4224 + 2*tc;
        const float* Ab = xcT + c*33*TM + tr*8;
        #pragma unroll 3
        for (int kk = 0; kk < 33; ++kk) {
            ulonglong2 a01 = *(const ulonglong2*)(Ab + kk*TM);      // rows 8tr..8tr+3 (broadcast)
            ulonglong2 a23 = *(const ulonglong2*)(Ab + kk*TM + 4);  // rows 8tr+4..8tr+7
            float2 bv = *(const float2*)(Wc + kk*128);
            unsigned long long b0, b1;
            PACK2(b0, bv.x); PACK2(b1, bv.y);
            FMA2(acc[0][0], a01.x, b0); FMA2(acc[0][1], a01.x, b1);
            FMA2(acc[1][0], a01.y, b0); FMA2(acc[1][1], a01.y, b1);
            FMA2(acc[2][0], a23.x, b0); FMA2(acc[2][1], a23.x, b1);
            FMA2(acc[3][0], a23.y, b0); FMA2(acc[3][1], a23.y, b1);
        }
        __syncthreads();
        buf ^= 1;
    }

    // epilogue: acc[r][c] = (row 8tr+2r, row 8tr+2r+1) at col 2tc+c
    size_t base = (size_t)(row0 + tr*8) * DD + 2*tc;
    #pragma unroll
    for (int r = 0; r < 4; r++) {
        float l0, h0, l1, h1;
        UNPK(l0, h0, acc[r][0]);
        UNPK(l1, h1, acc[r][1]);
        *(float2*)(g_z + base + (size_t)(2*r)*DD)   = make_float2(l0, l1);
        *(float2*)(g_z + base + (size_t)(2*r+1)*DD) = make_float2(h0, h1);
    }

    if (t < TM) {
        int n = (int)((row0 + t) % NSEQ);
        atomicAdd(&g_s1[n], sS[t]);
        atomicAdd(&g_q1[n], sQ[t]);
    }
}

// ---------------- k_fin1: BN1 finalize + colsum S (1 block, 256 threads) ----------------
__global__ void k_fin1(const float* __restrict__ Wg) {
    __shared__ float Ssh[DD];
    int t = threadIdx.x;
    if (t < NSEQ) {
        float cnt = (float)BB * (float)DCAT;
        float m = g_s1[t] / cnt;
        float v = g_q1[t] / cnt - m*m;
        g_is1[t] = rsqrtf(v + EPS_BN);
        g_m1[t]  = m;
    }
    int d = t & 127, h = t >> 7;        // two halves split the k-sum
    float S = 0.f;
    #pragma unroll 8
    for (int k = h; k < DCAT; k += 2) S += Wg[k*DD + d];
    if (h == 1) Ssh[d] = S;
    __syncthreads();
    if (h == 0) g_S[d] = S + Ssh[d];
}

// ---------------- k_mix: u = prelu(corr @ z_bn + bg) via rank-1 BN fold; BN2 stats ----------
__global__ __launch_bounds__(128)
void k_mix(const float* __restrict__ corr, const float* __restrict__ bg,
           const float* __restrict__ ag)
{
    __shared__ float2 cs[2*NSEQ*32];        // c'[n][m] duplicated as f32x2, m padded to 32
    __shared__ float qs[2*32];
    __shared__ float ssum[2*32], ssq[2*32];
    __shared__ float i1s[32], m1s[32];

    int t = threadIdx.x;
    int lb = t >> 6, lt = t & 63;
    int b = blockIdx.x * 2 + lb;

    unsigned long long zz[32];
    const float* zb = g_z + (size_t)b * NSEQ * DD + 2*lt;
    #pragma unroll
    for (int m = 0; m < NSEQ; m++) zz[m] = *(const unsigned long long*)(zb + m*DD);
    zz[29] = 0ull; zz[30] = 0ull; zz[31] = 0ull;

    if (t < NSEQ) { i1s[t] = g_is1[t]; m1s[t] = g_m1[t]; }
    if (t < 64) { ssum[t] = 0.f; ssq[t] = 0.f; }
    __syncthreads();

    {
        const float* cgb = corr + (size_t)b * NSEQ * NSEQ;
        for (int idx = lt; idx < NSEQ*32; idx += 64) {
            int n = idx >> 5, m = idx & 31;
            float v = (m < NSEQ) ? cgb[n*NSEQ + m] * i1s[m] : 0.f;
            cs[(lb*NSEQ + n)*32 + m] = make_float2(v, v);
        }
    }
    __syncthreads();

    if (lt < NSEQ) {
        float q = 0.f;
        #pragma unroll
        for (int m = 0; m < NSEQ; m++) q = fmaf(cs[(lb*NSEQ + lt)*32 + m].x, m1s[m], q);
        qs[lb*32 + lt] = q;
    }
    __syncthreads();

    float2 S2 = *(const float2*)(g_S + 2*lt);
    float2 bg2 = *(const float2*)(bg + 2*lt);
    float agv = ag[0];
    float* zg = g_z + (size_t)b * NSEQ * DD + 2*lt;
    int lane = t & 31;

    #pragma unroll 1
    for (int n = 0; n < NSEQ; n++) {
        const ulonglong2* cr = (const ulonglong2*)&cs[(lb*NSEQ + n)*32];
        unsigned long long acc = 0ull;
        #pragma unroll
        for (int ch = 0; ch < 16; ch++) {
            ulonglong2 cc = cr[ch];
            FMA2(acc, zz[2*ch],   cc.x);
            FMA2(acc, zz[2*ch+1], cc.y);
        }
        float u0, u1; UNPK(u0, u1, acc);
        float qn = qs[lb*32 + n];
        u0 = u0 - S2.x*qn + bg2.x;
        u1 = u1 - S2.y*qn + bg2.y;
        u0 = (u0 >= 0.f) ? u0 : agv*u0;
        u1 = (u1 >= 0.f) ? u1 : agv*u1;
        *(float2*)(zg + n*DD) = make_float2(u0, u1);
        float su = u0 + u1;
        float s2v = u0*u0 + u1*u1;
        #pragma unroll
        for (int o = 16; o > 0; o >>= 1) {
            su  += __shfl_down_sync(0xffffffffu, su,  o);
            s2v += __shfl_down_sync(0xffffffffu, s2v, o);
        }
        if (lane == 0) {
            atomicAdd(&ssum[lb*32 + n], su);
            atomicAdd(&ssq[lb*32 + n], s2v);
        }
    }
    __syncthreads();
    if (t < 2*NSEQ) {
        int lb2 = t / NSEQ, n = t - lb2*NSEQ;
        atomicAdd(&g_s2[n], ssum[lb2*32 + n]);
        atomicAdd(&g_q2[n], ssq[lb2*32 + n]);
    }
}

// ---------------- k_fin2: BN2 finalize + combined head vector v ----------------
__global__ void k_fin2(const float* __restrict__ cent, const float* __restrict__ hw) {
    __shared__ float nrm[4];
    int t = threadIdx.x;
    if (t < NSEQ) {
        float cnt = (float)BB * (float)DD;
        float m = g_s2[t] / cnt;
        float v = g_q2[t] / cnt - m*m;
        g_bn2m[t] = m; g_bn2i[t] = rsqrtf(v + EPS_BN);
    }
    if (t >= 32 && t < 36) {
        int h = t - 32; float s = 0.f;
        for (int d = 0; d < DD; d++) { float c = cent[h*DD + d]; s = fmaf(c, c, s); }
        nrm[h] = sqrtf(s) + 1e-8f;
    }
    __syncthreads();
    float v = 0.f;
    #pragma unroll
    for (int h = 0; h < 4; h++) v += hw[h] * cent[h*DD + t] / nrm[h];
    g_v[t] = v;
}

// ---------------- k_pool: BN2 apply + cosine-sim softmax pooling ----------------
__global__ __launch_bounds__(128)
void k_pool()
{
    __shared__ float xb[NSEQ*DD];
    __shared__ float vS[DD], m2[NSEQ], i2[NSEQ], aggS[32], CS[32];
    int t = threadIdx.x, b = blockIdx.x;
    if (t < NSEQ) { m2[t] = g_bn2m[t]; i2[t] = g_bn2i[t]; }
    vS[t] = g_v[t];
    __syncthreads();
    const float* ug = g_z + (size_t)b * NSEQ * DD;
    #pragma unroll 1
    for (int n = 0; n < NSEQ; n++) xb[n*DD + t] = (ug[n*DD + t] - m2[n]) * i2[n];
    __syncthreads();
    int w = t >> 5, l = t & 31;
    for (int n = w; n < NSEQ; n += 4) {
        float s2 = 0.f, sa = 0.f;
        #pragma unroll
        for (int dd = 0; dd < 4; dd++) {
            float x = xb[n*DD + l + dd*32];
            s2 = fmaf(x, x, s2);
            sa = fmaf(vS[l + dd*32], x, sa);
        }
        #pragma unroll
        for (int o = 16; o > 0; o >>= 1) {
            s2 += __shfl_down_sync(0xffffffffu, s2, o);
            sa += __shfl_down_sync(0xffffffffu, sa, o);
        }
        if (l == 0) aggS[n] = sa / (sqrtf(s2) + 1e-8f);
    }
    __syncthreads();
    if (w == 0) {
        float a = (l < NSEQ) ? aggS[l] : -1e30f;
        float mx = a;
        #pragma unroll
        for (int o = 16; o > 0; o >>= 1) mx = fmaxf(mx, __shfl_xor_sync(0xffffffffu, mx, o));
        float e = (l < NSEQ) ? expf(a - mx) : 0.f;
        float s = e;
        #pragma unroll
        for (int o = 16; o > 0; o >>= 1) s += __shfl_xor_sync(0xffffffffu, s, o);
        if (l < NSEQ) CS[l] = e / s;
    }
    __syncthreads();
    float p = 0.f;
    #pragma unroll 1
    for (int n = 0; n < NSEQ; n++) p = fmaf(CS[n], xb[n*DD + t], p);
    g_pool[(size_t)b*DD + t] = p;
}

// ---------------- k_projp: p = pooled @ Wp + bp; BN3 stats ----------------
__global__ __launch_bounds__(256)
void k_projp(const float* __restrict__ Wp, const float* __restrict__ bp)
{
    __shared__ float xs[64*DD];
    __shared__ float ss[DD], sq[DD];
    int t = threadIdx.x;
    size_t row0 = (size_t)blockIdx.x * 64;
    for (int i = t; i < 64*DD; i += 256) xs[i] = g_pool[row0*DD + i];
    if (t < DD) { ss[t] = 0.f; sq[t] = 0.f; }
    __syncthreads();
    int tc = t & 31, tr = t >> 5;
    float acc[8][4];
    #pragma unroll
    for (int i = 0; i < 8; i++)
        #pragma unroll
        for (int j = 0; j < 4; j++) acc[i][j] = 0.f;
    for (int k = 0; k < DD; k++) {
        float4 bv = *(const float4*)(Wp + k*DD + tc*4);
        #pragma unroll
        for (int i = 0; i < 8; i++) {
            float a = xs[(tr*8 + i)*DD + k];
            acc[i][0] = fmaf(a, bv.x, acc[i][0]);
            acc[i][1] = fmaf(a, bv.y, acc[i][1]);
            acc[i][2] = fmaf(a, bv.z, acc[i][2]);
            acc[i][3] = fmaf(a, bv.w, acc[i][3]);
        }
    }
    float4 bpv = *(const float4*)(bp + tc*4);
    float csum[4] = {0,0,0,0}, cq[4] = {0,0,0,0};
    #pragma unroll
    for (int i = 0; i < 8; i++) {
        float o0 = acc[i][0] + bpv.x, o1 = acc[i][1] + bpv.y;
        float o2 = acc[i][2] + bpv.z, o3 = acc[i][3] + bpv.w;
        *(float4*)(g_p + (row0 + tr*8 + i)*DD + tc*4) = make_float4(o0, o1, o2, o3);
        csum[0]+=o0; csum[1]+=o1; csum[2]+=o2; csum[3]+=o3;
        cq[0]=fmaf(o0,o0,cq[0]); cq[1]=fmaf(o1,o1,cq[1]); cq[2]=fmaf(o2,o2,cq[2]); cq[3]=fmaf(o3,o3,cq[3]);
    }
    #pragma unroll
    for (int j = 0; j < 4; j++) { atomicAdd(&ss[tc*4+j], csum[j]); atomicAdd(&sq[tc*4+j], cq[j]); }
    __syncthreads();
    if (t < DD) { atomicAdd(&g_s3[t], ss[t]); atomicAdd(&g_q3[t], sq[t]); }
}

__global__ void k_fin3() {
    int t = threadIdx.x;
    if (t < DD) {
        float m = g_s3[t] / (float)BB;
        float v = g_q3[t] / (float)BB - m*m;
        g_bn3m[t] = m; g_bn3i[t] = rsqrtf(v + EPS_BN);
    }
}

// ---------------- k_mlp ----------------
__global__ __launch_bounds__(128)
void k_mlp(const float* __restrict__ Wm1, const float* __restrict__ bm1,
           const float* __restrict__ am, const float* __restrict__ Wm2,
           const float* __restrict__ bm2, float* __restrict__ out)
{
    __shared__ float xbn[16*DD];
    __shared__ float sg[16*DD];
    int t = threadIdx.x;
    size_t row0 = (size_t)blockIdx.x * 16;
    for (int i = t; i < 16*DD; i += 128) {
        int k = i & 127;
        xbn[i] = (g_p[row0*DD + i] - g_bn3m[k]) * g_bn3i[k];
    }
    __syncthreads();
    float amv = am[0], w2 = Wm2[t], b1v = bm1[t];
    float acc[16];
    #pragma unroll
    for (int r = 0; r < 16; r++) acc[r] = b1v;
    #pragma unroll 4
    for (int k = 0; k < DD; k++) {
        float wv = Wm1[k*DD + t];
        #pragma unroll
        for (int r = 0; r < 16; r++) acc[r] = fmaf(xbn[r*DD + k], wv, acc[r]);
    }
    #pragma unroll
    for (int r = 0; r < 16; r++) {
        float h = acc[r];
        h = (h >= 0.f) ? h : amv*h;
        sg[r*DD + t] = h * w2;
    }
    __syncthreads();
    int w = t >> 5, l = t & 31;
    float b2 = bm2[0];
    #pragma unroll
    for (int rr = 0; rr < 4; rr++) {
        int r = w*4 + rr;
        float s = sg[r*DD + l] + sg[r*DD + l + 32] + sg[r*DD + l + 64] + sg[r*DD + l + 96];
        #pragma unroll
        for (int o = 16; o > 0; o >>= 1) s += __shfl_down_sync(0xffffffffu, s, o);
        if (l == 0) out[row0 + r] = 1.f / (1.f + expf(-(s + b2)));
    }
}

// ---------------- launch ----------------
extern "C" void kernel_launch(void* const* d_in, const int* in_sizes, int n_in,
                              void* d_out, int out_size) {
    const float* X    = (const float*)d_in[0];
    const float* corr = (const float*)d_in[1];
    const float* w1   = (const float*)d_in[2];
    const float* b1   = (const float*)d_in[3];
    const float* w2   = (const float*)d_in[4];
    const float* b2   = (const float*)d_in[5];
    const float* w3   = (const float*)d_in[6];
    const float* b3   = (const float*)d_in[7];
    const float* ac   = (const float*)d_in[8];
    const float* Wg   = (const float*)d_in[9];
    const float* bg   = (const float*)d_in[10];
    const float* ag   = (const float*)d_in[11];
    const float* cent = (const float*)d_in[12];
    const float* hw   = (const float*)d_in[13];
    const float* Wp   = (const float*)d_in[14];
    const float* bp   = (const float*)d_in[15];
    const float* Wm1  = (const float*)d_in[16];
    const float* bm1  = (const float*)d_in[17];
    const float* am   = (const float*)d_in[18];
    const float* Wm2  = (const float*)d_in[19];
    const float* bm2  = (const float*)d_in[20];
    float* out = (float*)d_out;

    cudaFuncSetAttribute(k_gemm, cudaFuncAttributeMaxDynamicSharedMemorySize, GEMM_SMEM);

    k_reset<<<1, 128>>>();
    k_gemm<<<NROWS/TM, 256, GEMM_SMEM>>>(X, Wg, w1, b1, w2, b2, w3, b3, ac);
    k_fin1<<<1, 256>>>(Wg);
    k_mix<<<BB/2, 128>>>(corr, bg, ag);
    k_fin2<<<1, 128>>>(cent, hw);
    k_pool<<<BB, 128>>>();
    k_projp<<<BB/64, 256>>>(Wp, bp);
    k_fin3<<<1, 128>>>();
    k_mlp<<<BB/16, 128>>>(Wm1, bm1, am, Wm2, bm2, out);
}